// round 2
// baseline (speedup 1.0000x reference)
#include <cuda_runtime.h>
#include <cstdint>

// CostBuilder: stereo cost-volume construction.
// left, right: (B=4, C=32, H=64, W=128) fp32
// out:         (B, 2C=64, D=48, H, W) fp32
//   out[b, c,   d, h, w] = (w>=d) ? left [b,c,h,w]   : 0
//   out[b, C+c, d, h, w] = (w>=d) ? right[b,c,h,w-d] : 0
//
// HBM-store-bound (~403 MB out). One block per (b,c,h). Right row staged in
// shared with a bank-swizzled layout so the shifted reads in the d-loop are
// conflict-free; left row lives in registers. float4 (STG.128) stores.

namespace {
constexpr int B = 4;
constexpr int C = 32;
constexpr int H = 64;
constexpr int W = 128;
constexpr int D = 48;            // MAX_DISP / 4
constexpr int TPB = 256;         // 8 warps
constexpr int WARPS = TPB / 32;
constexpr unsigned HW = H * W;   // 8192

// Swizzled position for shared right-row: pos(w) = (w%4)*32 + w/4.
// In the d-loop, lanes access w-d = 4*lane + m (m fixed per j,d), so
// pos>>? : idx>>2 = lane + const  ->  consecutive banks, conflict-free.
__device__ __forceinline__ int swz(int w) { return ((w & 3) << 5) | (w >> 2); }
}

__global__ __launch_bounds__(TPB) void cost_builder_kernel(
    const float* __restrict__ left,
    const float* __restrict__ right,
    float* __restrict__ out)
{
    const int bch = blockIdx.x;          // enumerates (b*C + c)*H + h
    const int h   = bch % H;
    const int bc  = bch / H;             // b*C + c
    const int c   = bc % C;
    const int b   = bc / C;

    __shared__ float s_right[W];

    const float* lrow = left  + ((size_t)bc * H + h) * W;
    const float* rrow = right + ((size_t)bc * H + h) * W;

    const int tid  = threadIdx.x;
    const int lane = tid & 31;
    const int warp = tid >> 5;
    const int w0   = lane << 2;          // this lane's first w (float4 group)

    // Stage right row into swizzled shared: thread t writes s[t] (conflict-free
    // STS) from the matching gmem element. pos(w)=t  <=>  w = 4*(t&31)+(t>>5).
    if (tid < W) {
        s_right[tid] = rrow[((tid & 31) << 2) + (tid >> 5)];
    }

    // Left values this lane owns, registers across all d.
    const float4 lv = reinterpret_cast<const float4*>(lrow)[lane];

    __syncthreads();

    // Output offsets fit in 32 bits (100.7M elements).
    const unsigned chL   = (unsigned)(b * 2 * C + c);
    const unsigned baseL = (chL * D) * HW       + (unsigned)h * W + (unsigned)w0;
    const unsigned baseR = ((chL + C) * D) * HW + (unsigned)h * W + (unsigned)w0;

    #pragma unroll
    for (int k = 0; k < D / WARPS; ++k) {
        const int d = warp + k * WARPS;

        float4 ov;
        ov.x = (w0     >= d) ? lv.x : 0.0f;
        ov.y = (w0 + 1 >= d) ? lv.y : 0.0f;
        ov.z = (w0 + 2 >= d) ? lv.z : 0.0f;
        ov.w = (w0 + 3 >= d) ? lv.w : 0.0f;

        const int i0 = w0 - d;           // w - d for j = 0
        float4 rv;
        rv.x = (i0     >= 0) ? s_right[swz(i0    )] : 0.0f;
        rv.y = (i0 + 1 >= 0) ? s_right[swz(i0 + 1)] : 0.0f;
        rv.z = (i0 + 2 >= 0) ? s_right[swz(i0 + 2)] : 0.0f;
        rv.w = (i0 + 3 >= 0) ? s_right[swz(i0 + 3)] : 0.0f;

        const unsigned du = (unsigned)d * HW;
        *reinterpret_cast<float4*>(out + baseL + du) = ov;
        *reinterpret_cast<float4*>(out + baseR + du) = rv;
    }
}

extern "C" void kernel_launch(void* const* d_in, const int* in_sizes, int n_in,
                              void* d_out, int out_size)
{
    const float* left  = (const float*)d_in[0];
    const float* right = (const float*)d_in[1];
    float* out = (float*)d_out;

    const int grid = B * C * H;          // 8192 blocks
    cost_builder_kernel<<<grid, TPB>>>(left, right, out);
}

// round 3
// speedup vs baseline: 1.1033x; 1.1033x over previous
#include <cuda_runtime.h>
#include <cstdint>

// CostBuilder: stereo cost-volume construction.
// left, right: (B=4, C=32, H=64, W=128) fp32
// out:         (B, 2C=64, D=48, H, W) fp32
//   out[b, c,   d, h, w] = (w>=d) ? left [b,c,h,w]   : 0
//   out[b, C+c, d, h, w] = (w>=d) ? right[b,c,h,w-d] : 0
//
// R3: DRAM-write-locality layout. One block owns (plane, 3 consecutive d) =
// 96KB of CONTIGUOUS output, written sequentially for HBM page locality.
// Input plane (32KB) staged once in bank-swizzled shared; streaming stores.

namespace {
constexpr int B   = 4;
constexpr int C   = 32;
constexpr int H   = 64;
constexpr int W   = 128;
constexpr int D   = 48;              // MAX_DISP / 4
constexpr int HW  = H * W;           // 8192
constexpr int TPB = 256;
constexpr int DPB = 3;               // d values per block
constexpr int NDG = D / DPB;         // 16 d-groups
constexpr int PASSES = HW / 4 / TPB; // 8 float4 passes per plane

// Per-row bank swizzle: pos(w) = (w%4)*32 + w/4. For lane-parallel access at
// w = 4*lane + e, idx>>2 = lane + const -> consecutive banks, conflict-free.
__device__ __forceinline__ int swz(int w) { return ((w & 3) << 5) | (w >> 2); }
}

__global__ __launch_bounds__(TPB) void cost_builder_kernel(
    const float* __restrict__ left,
    const float* __restrict__ right,
    float* __restrict__ out)
{
    const int g    = blockIdx.x;
    const int dg   = g & (NDG - 1);      // d-group 0..15
    const int bc2  = g >> 4;             // output channel-plane 0..255
    const int b    = bc2 >> 6;
    const int ch   = bc2 & 63;
    const bool is_right = ch >= C;
    const int c    = ch & (C - 1);

    const float* src = (is_right ? right : left) + (size_t)(b * C + c) * HW;

    __shared__ float s[HW];              // 32KB plane, per-row swizzled

    const int tid  = threadIdx.x;
    const int lane = tid & 31;

    // Stage input plane into swizzled shared. Thread handles float4 group i;
    // each warp covers one full row per pass. STS addresses per j are
    // lane-consecutive -> conflict-free.
    #pragma unroll
    for (int p = 0; p < PASSES; ++p) {
        const int i = p * TPB + tid;
        const float4 v = reinterpret_cast<const float4*>(src)[i];
        const int rowbase = (i >> 5) * W;
        s[rowbase +  0 + lane] = v.x;
        s[rowbase + 32 + lane] = v.y;
        s[rowbase + 64 + lane] = v.z;
        s[rowbase + 96 + lane] = v.w;
    }
    __syncthreads();

    // This block's contiguous output region: plane bc2, d in [d0, d0+DPB).
    const unsigned outbase0 = (unsigned)bc2 * D * HW;
    const int d0 = dg * DPB;

    #pragma unroll
    for (int dd = 0; dd < DPB; ++dd) {
        const int d     = d0 + dd;
        const int shift = is_right ? d : 0;
        float4* outp = reinterpret_cast<float4*>(out + outbase0 + (unsigned)d * HW);

        #pragma unroll
        for (int p = 0; p < PASSES; ++p) {
            const int i = p * TPB + tid;
            const int rowbase = (i >> 5) * W;
            const int w  = lane << 2;            // warp spans one full row
            const int q0 = w - shift;

            float4 v;
            // Clamp keeps speculative LDS in-bounds; mask selects 0 for w<d.
            v.x = (w     >= d) ? s[rowbase + swz(q0 < 0 ? 0 : q0)]     : 0.0f;
            v.y = (w + 1 >= d) ? s[rowbase + swz(q0 + 1 < 0 ? 0 : q0 + 1)] : 0.0f;
            v.z = (w + 2 >= d) ? s[rowbase + swz(q0 + 2 < 0 ? 0 : q0 + 2)] : 0.0f;
            v.w = (w + 3 >= d) ? s[rowbase + swz(q0 + 3 < 0 ? 0 : q0 + 3)] : 0.0f;

            __stcs(outp + i, v);                 // streaming store, evict-first
        }
    }
}

extern "C" void kernel_launch(void* const* d_in, const int* in_sizes, int n_in,
                              void* d_out, int out_size)
{
    const float* left  = (const float*)d_in[0];
    const float* right = (const float*)d_in[1];
    float* out = (float*)d_out;

    const int grid = (2 * B * C) * NDG;   // 256 planes * 16 d-groups = 4096
    cost_builder_kernel<<<grid, TPB>>>(left, right, out);
}